// round 3
// baseline (speedup 1.0000x reference)
#include <cuda_runtime.h>

// PointNetSaModule: gather(K=16) -> mask -> [67->64->64->128] MLP (BN folded) -> max over K.
// Warp-cooperative register tiling: warp owns 32 rows (2 groups of K=16).
// Thread tile = 4 rows x 16 channels; fp32 math via packed fma.rn.f32x2.

typedef unsigned long long ULL;

#define HW_SZ  65536
#define NS_SZ  16384
#define K_SZ   16
#define OUT_ONE (4 * 16384 * 128)

#define THREADS 512
#define WARPS   16
#define RS      68          // act row stride (floats); float4-aligned, conflict-free reads

// smem float offsets
#define OFF_W0   0                  // 67*64 (rows permuted: feats first, xyz-diff last)
#define OFF_W1   4288               // 64*64
#define OFF_W2   (4288 + 4096)      // 64*128
#define OFF_T0   (OFF_W2 + 8192)    // 64
#define OFF_T1   (OFF_T0 + 64)      // 64
#define OFF_T2   (OFF_T1 + 64)      // 128
#define OFF_S0   (OFF_T2 + 128)     // 64
#define OFF_S1   (OFF_S0 + 64)      // 64
#define OFF_S2   (OFF_S1 + 64)      // 128
#define OFF_ACT  (OFF_S2 + 128)
#define SMEM_FLOATS (OFF_ACT + WARPS * 32 * RS)   // 51904
#define SMEM_BYTES  (SMEM_FLOATS * 4)             // 207616 B

__device__ __forceinline__ ULL pack2_dup(float v) {
    ULL r; asm("mov.b64 %0, {%1, %1};" : "=l"(r) : "f"(v)); return r;
}
__device__ __forceinline__ float2 unpack2(ULL v) {
    float2 f; asm("mov.b64 {%0, %1}, %2;" : "=f"(f.x), "=f"(f.y) : "l"(v)); return f;
}
__device__ __forceinline__ void ffma2(ULL& acc, ULL x, ULL w) {
    asm("fma.rn.f32x2 %0, %1, %2, %0;" : "+l"(acc) : "l"(x), "l"(w));
}

// One cin step: weights for this thread's 16 channels + dup-broadcast acts for 4 rows.
__device__ __forceinline__ void step_cin(ULL acc[32], const float* wrow,
                                         float a0, float a1, float a2, float a3)
{
    const ulonglong2* wp = (const ulonglong2*)wrow;
    ulonglong2 wA = wp[0], wB = wp[1], wC = wp[2], wD = wp[3];
    ULL x;
    x = pack2_dup(a0);
    ffma2(acc[0], x, wA.x); ffma2(acc[1], x, wA.y); ffma2(acc[2], x, wB.x); ffma2(acc[3], x, wB.y);
    ffma2(acc[4], x, wC.x); ffma2(acc[5], x, wC.y); ffma2(acc[6], x, wD.x); ffma2(acc[7], x, wD.y);
    x = pack2_dup(a1);
    ffma2(acc[8],  x, wA.x); ffma2(acc[9],  x, wA.y); ffma2(acc[10], x, wB.x); ffma2(acc[11], x, wB.y);
    ffma2(acc[12], x, wC.x); ffma2(acc[13], x, wC.y); ffma2(acc[14], x, wD.x); ffma2(acc[15], x, wD.y);
    x = pack2_dup(a2);
    ffma2(acc[16], x, wA.x); ffma2(acc[17], x, wA.y); ffma2(acc[18], x, wB.x); ffma2(acc[19], x, wB.y);
    ffma2(acc[20], x, wC.x); ffma2(acc[21], x, wC.y); ffma2(acc[22], x, wD.x); ffma2(acc[23], x, wD.y);
    x = pack2_dup(a3);
    ffma2(acc[24], x, wA.x); ffma2(acc[25], x, wA.y); ffma2(acc[26], x, wB.x); ffma2(acc[27], x, wB.y);
    ffma2(acc[28], x, wC.x); ffma2(acc[29], x, wC.y); ffma2(acc[30], x, wD.x); ffma2(acc[31], x, wD.y);
}

__device__ __forceinline__ void gemm_tile(ULL acc[32],
    const float* a0, const float* a1, const float* a2, const float* a3,
    const float* wb, int ws, int nchunk)
{
    #pragma unroll 2
    for (int c4 = 0; c4 < nchunk; c4++) {
        float4 v0 = *(const float4*)(a0 + c4 * 4);
        float4 v1 = *(const float4*)(a1 + c4 * 4);
        float4 v2 = *(const float4*)(a2 + c4 * 4);
        float4 v3 = *(const float4*)(a3 + c4 * 4);
        const float* wr = wb + c4 * 4 * ws;
        step_cin(acc, wr,          v0.x, v1.x, v2.x, v3.x);
        step_cin(acc, wr + ws,     v0.y, v1.y, v2.y, v3.y);
        step_cin(acc, wr + 2 * ws, v0.z, v1.z, v2.z, v3.z);
        step_cin(acc, wr + 3 * ws, v0.w, v1.w, v2.w, v3.w);
    }
}

// bias + ReLU + store 16 channels for 4 rows back to act rows (in-place, pre/post syncwarp by caller)
__device__ __forceinline__ void store_relu(ULL acc[32],
    float* a0, float* a1, float* a2, float* a3,
    const float* T, int chbase)
{
    float4 bt[4];
    #pragma unroll
    for (int j = 0; j < 4; j++) bt[j] = ((const float4*)(T + chbase))[j];
    float* rows[4] = {a0, a1, a2, a3};
    #pragma unroll
    for (int r = 0; r < 4; r++) {
        float* dst = rows[r] + chbase;
        #pragma unroll
        for (int j = 0; j < 4; j++) {
            float2 p0 = unpack2(acc[r * 8 + 2 * j]);
            float2 p1 = unpack2(acc[r * 8 + 2 * j + 1]);
            float4 o;
            o.x = fmaxf(p0.x + bt[j].x, 0.f);
            o.y = fmaxf(p0.y + bt[j].y, 0.f);
            o.z = fmaxf(p1.x + bt[j].z, 0.f);
            o.w = fmaxf(p1.y + bt[j].w, 0.f);
            *(float4*)(dst + 4 * j) = o;
        }
    }
}

__global__ void __launch_bounds__(THREADS, 1)
pointnet_sa_kernel(
    const float* __restrict__ xyz, const float* __restrict__ pts,
    const float* __restrict__ xyzs, const int* __restrict__ nbr,
    const float* __restrict__ vmask,
    const float* __restrict__ w0, const float* __restrict__ b0,
    const float* __restrict__ g0, const float* __restrict__ be0,
    const float* __restrict__ m0, const float* __restrict__ v0,
    const float* __restrict__ w1, const float* __restrict__ b1,
    const float* __restrict__ g1, const float* __restrict__ be1,
    const float* __restrict__ m1, const float* __restrict__ v1,
    const float* __restrict__ w2, const float* __restrict__ b2,
    const float* __restrict__ g2, const float* __restrict__ be2,
    const float* __restrict__ m2, const float* __restrict__ v2,
    float* __restrict__ out, int copies)
{
    extern __shared__ float sm[];
    const int tid = threadIdx.x;

    // ---- BN fold ----
    if (tid < 64) {
        float s = g0[tid] * rsqrtf(v0[tid] + 1e-5f);
        sm[OFF_S0 + tid] = s;
        sm[OFF_T0 + tid] = (b0[tid] - m0[tid]) * s + be0[tid];
        float s1 = g1[tid] * rsqrtf(v1[tid] + 1e-5f);
        sm[OFF_S1 + tid] = s1;
        sm[OFF_T1 + tid] = (b1[tid] - m1[tid]) * s1 + be1[tid];
    }
    if (tid < 128) {
        float s = g2[tid] * rsqrtf(v2[tid] + 1e-5f);
        sm[OFF_S2 + tid] = s;
        sm[OFF_T2 + tid] = (b2[tid] - m2[tid]) * s + be2[tid];
    }
    __syncthreads();
    // W0 with row permutation: smem row i (i<64) = point-chan i = src row 3+i;
    // smem rows 64..66 = xyz-diff = src rows 0..2.
    for (int i = tid; i < 4288; i += THREADS) {
        int r = i >> 6, c = i & 63;
        int sr = (r < 64) ? (r + 3) : (r - 64);
        sm[OFF_W0 + i] = w0[sr * 64 + c] * sm[OFF_S0 + c];
    }
    for (int i = tid; i < 4096; i += THREADS) sm[OFF_W1 + i] = w1[i] * sm[OFF_S1 + (i & 63)];
    for (int i = tid; i < 8192; i += THREADS) sm[OFF_W2 + i] = w2[i] * sm[OFF_S2 + (i & 127)];
    __syncthreads();

    const int lane   = tid & 31;
    const int warp   = tid >> 5;
    const int lane_c = lane & 3;
    const int lane_r = lane >> 2;
    float* actw = sm + OFF_ACT + warp * 32 * RS;

    // ---- gather: lane owns row=lane; layout [p0..p63, d0,d1,d2] ----
    {
        const int grp = blockIdx.x * 32 + warp * 2 + (lane >> 4);
        const int b = grp >> 14;
        const int n = grp & (NS_SZ - 1);
        const int e = grp * K_SZ + (lane & 15);
        const int idx = nbr[e];
        const float mk = vmask[e];
        float* xr = actw + lane * RS;
        const float4* pp = (const float4*)(pts + (b * HW_SZ + idx) * 64);
        #pragma unroll
        for (int i = 0; i < 16; i++) {
            float4 p = pp[i];
            p.x *= mk; p.y *= mk; p.z *= mk; p.w *= mk;
            *(float4*)(xr + 4 * i) = p;
        }
        const float* cp = xyzs + (b * NS_SZ + n) * 3;
        const float* gx = xyz + (b * HW_SZ + idx) * 3;
        xr[64] = gx[0] * mk - cp[0];
        xr[65] = gx[1] * mk - cp[1];
        xr[66] = gx[2] * mk - cp[2];
    }
    __syncwarp();

    // thread's 4 act rows (all inside one K-group: lane_r 0-3 -> rows 0-15)
    float* a0 = actw + (lane_r * 4 + 0) * RS;
    float* a1 = actw + (lane_r * 4 + 1) * RS;
    float* a2 = actw + (lane_r * 4 + 2) * RS;
    float* a3 = actw + (lane_r * 4 + 3) * RS;
    const int chbase = lane_c * 16;

    // ---- layer 0: 67 -> 64 ----
    {
        ULL acc[32];
        #pragma unroll
        for (int j = 0; j < 32; j++) acc[j] = 0ull;
        const float* wb = sm + OFF_W0 + chbase;
        gemm_tile(acc, a0, a1, a2, a3, wb, 64, 16);
        #pragma unroll
        for (int j = 0; j < 3; j++)   // remainder rows 64..66 (xyz diff)
            step_cin(acc, wb + (64 + j) * 64, a0[64 + j], a1[64 + j], a2[64 + j], a3[64 + j]);
        __syncwarp();
        store_relu(acc, a0, a1, a2, a3, sm + OFF_T0, chbase);
        __syncwarp();
    }

    // ---- layer 1: 64 -> 64 ----
    {
        ULL acc[32];
        #pragma unroll
        for (int j = 0; j < 32; j++) acc[j] = 0ull;
        gemm_tile(acc, a0, a1, a2, a3, sm + OFF_W1 + chbase, 64, 16);
        __syncwarp();
        store_relu(acc, a0, a1, a2, a3, sm + OFF_T1, chbase);
        __syncwarp();
    }

    // ---- layer 2: 64 -> 128 in two 64-channel passes; fused max-pool ----
    const int grp_out = blockIdx.x * 32 + warp * 2 + (lane >> 4);
    const long base = (long)grp_out * 128;
    const bool writer = ((lane & 12) == 0);   // lane_r == 0 within each 16-lane group

    #pragma unroll
    for (int p = 0; p < 2; p++) {
        ULL acc[32];
        #pragma unroll
        for (int j = 0; j < 32; j++) acc[j] = 0ull;
        gemm_tile(acc, a0, a1, a2, a3, sm + OFF_W2 + p * 64 + chbase, 128, 16);

        // max over this thread's 4 rows (bias/ReLU commute with max)
        float mx[16];
        #pragma unroll
        for (int j = 0; j < 8; j++) {
            float2 r0 = unpack2(acc[j]);
            float2 r1 = unpack2(acc[8 + j]);
            float2 r2 = unpack2(acc[16 + j]);
            float2 r3 = unpack2(acc[24 + j]);
            mx[2 * j]     = fmaxf(fmaxf(r0.x, r1.x), fmaxf(r2.x, r3.x));
            mx[2 * j + 1] = fmaxf(fmaxf(r0.y, r1.y), fmaxf(r2.y, r3.y));
        }
        // reduce across lane_r within group: xor offsets 4, 8 (stay within 16-lane half)
        #pragma unroll
        for (int off = 4; off <= 8; off <<= 1) {
            #pragma unroll
            for (int j = 0; j < 16; j++) {
                float o = __shfl_xor_sync(0xffffffffu, mx[j], off);
                mx[j] = fmaxf(mx[j], o);
            }
        }
        if (writer) {
            const float* T = sm + OFF_T2 + p * 64 + chbase;
            const long off0 = base + p * 64 + chbase;
            #pragma unroll
            for (int j = 0; j < 4; j++) {
                float4 bt = ((const float4*)T)[j];
                float4 o;
                o.x = fmaxf(mx[4 * j + 0] + bt.x, 0.f);
                o.y = fmaxf(mx[4 * j + 1] + bt.y, 0.f);
                o.z = fmaxf(mx[4 * j + 2] + bt.z, 0.f);
                o.w = fmaxf(mx[4 * j + 3] + bt.w, 0.f);
                *(float4*)(out + off0 + 4 * j) = o;
                if (copies > 1) *(float4*)(out + OUT_ONE + off0 + 4 * j) = o;
            }
        }
    }
}

extern "C" void kernel_launch(void* const* d_in, const int* in_sizes, int n_in,
                              void* d_out, int out_size)
{
    const float* xyz   = (const float*)d_in[0];
    const float* pts   = (const float*)d_in[1];
    const float* xyzs  = (const float*)d_in[2];
    const int*   nbr   = (const int*)  d_in[3];
    const float* vmask = (const float*)d_in[4];
    const float* w0  = (const float*)d_in[5];
    const float* b0  = (const float*)d_in[6];
    const float* g0  = (const float*)d_in[7];
    const float* be0 = (const float*)d_in[8];
    const float* m0  = (const float*)d_in[9];
    const float* v0  = (const float*)d_in[10];
    const float* w1  = (const float*)d_in[11];
    const float* b1  = (const float*)d_in[12];
    const float* g1  = (const float*)d_in[13];
    const float* be1 = (const float*)d_in[14];
    const float* m1  = (const float*)d_in[15];
    const float* v1  = (const float*)d_in[16];
    const float* w2  = (const float*)d_in[17];
    const float* b2  = (const float*)d_in[18];
    const float* g2  = (const float*)d_in[19];
    const float* be2 = (const float*)d_in[20];
    const float* m2  = (const float*)d_in[21];
    const float* v2  = (const float*)d_in[22];

    int copies = (out_size >= 2 * OUT_ONE) ? 2 : 1;

    cudaFuncSetAttribute(pointnet_sa_kernel,
                         cudaFuncAttributeMaxDynamicSharedMemorySize, SMEM_BYTES);

    const int blocks = (4 * NS_SZ) / 32;   // 2048 (32 groups per block)
    pointnet_sa_kernel<<<blocks, THREADS, SMEM_BYTES>>>(
        xyz, pts, xyzs, nbr, vmask,
        w0, b0, g0, be0, m0, v0,
        w1, b1, g1, be1, m1, v1,
        w2, b2, g2, be2, m2, v2,
        (float*)d_out, copies);
}

// round 5
// speedup vs baseline: 1.3486x; 1.3486x over previous
#include <cuda_runtime.h>

// PointNetSaModule: gather(K=16) -> mask -> [67->64->64->128] MLP (BN folded) -> max over K.
// Row-pair packed FFMA2: acc = (out[rowA][ch], out[rowB][ch]).
//  - activation operand: broadcast pair from smem (same addr all lanes, conflict-free)
//  - weight operand: per-lane dup, loaded ONCE per cin (LDS.64) and reused over 16 pairs
//  - max-pool over K=16 is thread-local (thread holds all pairs of its 2 channels)

typedef unsigned long long ULL;

#define HW_SZ  65536
#define NS_SZ  16384
#define OUT_ONE (4 * 16384 * 128)

#define THREADS 512
#define WARPS   16

// smem float offsets
#define OFF_W0   0                  // 67*64 (rows permuted: feats 0..63, xyz-diff 64..66)
#define OFF_W1   4288               // 64*64
#define OFF_W2   (4288 + 4096)      // 64*128
#define OFF_T0   (OFF_W2 + 8192)
#define OFF_T1   (OFF_T0 + 64)
#define OFF_T2   (OFF_T1 + 64)
#define OFF_S0   (OFF_T2 + 128)
#define OFF_S1   (OFF_S0 + 64)
#define OFF_S2   (OFF_S1 + 64)
#define OFF_ACT  (OFF_S2 + 128)     // 17088 -> byte 68352, 16B aligned
// act tile per warp: 68 cins x 16 row-pairs (ULL) = 1088 ULL = 2176 floats
#define ACT_ULL_PER_WARP 1088
#define SMEM_FLOATS (OFF_ACT + WARPS * 2 * ACT_ULL_PER_WARP)   // 51904
#define SMEM_BYTES  (SMEM_FLOATS * 4)                          // 207616

__device__ __forceinline__ ULL pack2_dup(float v) {
    ULL r; asm("mov.b64 %0, {%1, %1};" : "=l"(r) : "f"(v)); return r;
}
__device__ __forceinline__ ULL pack2(float a, float b) {
    ULL r; asm("mov.b64 %0, {%1, %2};" : "=l"(r) : "f"(a), "f"(b)); return r;
}
__device__ __forceinline__ float2 unpack2(ULL v) {
    float2 f; asm("mov.b64 {%0, %1}, %2;" : "=f"(f.x), "=f"(f.y) : "l"(v)); return f;
}
__device__ __forceinline__ void ffma2(ULL& acc, ULL x, ULL w) {
    asm("fma.rn.f32x2 %0, %1, %2, %0;" : "+l"(acc) : "l"(x), "l"(w));
}

// act layout: ULL index = cin*16 + (pair ^ sw(cin)), sw(cin) = 2*((cin>>1)&7)
// sw is even -> logical pair (2q,2q+1) stays physically adjacent -> LDS.128 reads.

// acc[2p+s] = (out[row 2p][ch_s], out[row 2p+1][ch_s]), ch_s = choff + 2*lane + s
__device__ __forceinline__ void run_layer(ULL acc[32], const ULL* __restrict__ actw,
        const float* __restrict__ W, int ncin, int wstride, int choff, int lane)
{
    #pragma unroll 2
    for (int c = 0; c < ncin; c++) {
        float2 wv = *(const float2*)(W + c * wstride + choff + 2 * lane);
        ULL w0 = pack2_dup(wv.x);
        ULL w1 = pack2_dup(wv.y);
        const ULL* xrow = actw + c * 16;
        const int sw = ((c >> 1) & 7) * 2;
        #pragma unroll
        for (int q = 0; q < 8; q++) {
            ulonglong2 x2 = *(const ulonglong2*)(xrow + ((2 * q) ^ sw));
            ffma2(acc[4*q + 0], x2.x, w0);
            ffma2(acc[4*q + 1], x2.x, w1);
            ffma2(acc[4*q + 2], x2.y, w0);
            ffma2(acc[4*q + 3], x2.y, w1);
        }
    }
}

// bias + ReLU + write back as next layer's activations (channels = next cins)
__device__ __forceinline__ void epilogue_store(ULL acc[32], ULL* __restrict__ actw,
        const float* __restrict__ T, int lane)
{
    const float t0 = T[2 * lane];
    const float t1 = T[2 * lane + 1];
    const int sw = (lane & 7) * 2;      // sw(ch) for ch = 2*lane, 2*lane+1
    ULL* r0 = actw + (2 * lane) * 16;
    ULL* r1 = actw + (2 * lane + 1) * 16;
    #pragma unroll
    for (int p = 0; p < 16; p++) {
        const int pp = p ^ sw;
        float2 a = unpack2(acc[2 * p]);
        float2 b = unpack2(acc[2 * p + 1]);
        r0[pp] = pack2(fmaxf(a.x + t0, 0.f), fmaxf(a.y + t0, 0.f));
        r1[pp] = pack2(fmaxf(b.x + t1, 0.f), fmaxf(b.y + t1, 0.f));
    }
}

__global__ void __launch_bounds__(THREADS, 1)
pointnet_sa_kernel(
    const float* __restrict__ xyz, const float* __restrict__ pts,
    const float* __restrict__ xyzs, const int* __restrict__ nbr,
    const float* __restrict__ vmask,
    const float* __restrict__ w0, const float* __restrict__ b0,
    const float* __restrict__ g0, const float* __restrict__ be0,
    const float* __restrict__ m0, const float* __restrict__ v0,
    const float* __restrict__ w1, const float* __restrict__ b1,
    const float* __restrict__ g1, const float* __restrict__ be1,
    const float* __restrict__ m1, const float* __restrict__ v1,
    const float* __restrict__ w2, const float* __restrict__ b2,
    const float* __restrict__ g2, const float* __restrict__ be2,
    const float* __restrict__ m2, const float* __restrict__ v2,
    float* __restrict__ out, int copies)
{
    extern __shared__ float sm[];
    const int tid = threadIdx.x;

    // ---- BN fold ----
    if (tid < 64) {
        float s = g0[tid] * rsqrtf(v0[tid] + 1e-5f);
        sm[OFF_S0 + tid] = s;
        sm[OFF_T0 + tid] = (b0[tid] - m0[tid]) * s + be0[tid];
        float s1 = g1[tid] * rsqrtf(v1[tid] + 1e-5f);
        sm[OFF_S1 + tid] = s1;
        sm[OFF_T1 + tid] = (b1[tid] - m1[tid]) * s1 + be1[tid];
    }
    if (tid < 128) {
        float s = g2[tid] * rsqrtf(v2[tid] + 1e-5f);
        sm[OFF_S2 + tid] = s;
        sm[OFF_T2 + tid] = (b2[tid] - m2[tid]) * s + be2[tid];
    }
    __syncthreads();
    // W0 permuted: smem row i<64 = src row 3+i (feats); rows 64..66 = src 0..2 (xyz diff)
    for (int i = tid; i < 4288; i += THREADS) {
        int r = i >> 6, c = i & 63;
        int sr = (r < 64) ? (r + 3) : (r - 64);
        sm[OFF_W0 + i] = w0[sr * 64 + c] * sm[OFF_S0 + c];
    }
    for (int i = tid; i < 4096; i += THREADS) sm[OFF_W1 + i] = w1[i] * sm[OFF_S1 + (i & 63)];
    for (int i = tid; i < 8192; i += THREADS) sm[OFF_W2 + i] = w2[i] * sm[OFF_S2 + (i & 127)];
    __syncthreads();

    const int lane = tid & 31;
    const int warp = tid >> 5;
    ULL* actw = (ULL*)(sm + OFF_ACT) + warp * ACT_ULL_PER_WARP;
    float* actwf = (float*)actw;

    // ---- gather: lane owns row=lane (rows 0-15 -> group 0, 16-31 -> group 1) ----
    {
        const int grp = blockIdx.x * 32 + warp * 2 + (lane >> 4);
        const int b = grp >> 14;
        const int n = grp & (NS_SZ - 1);
        const int e = grp * 16 + (lane & 15);
        const int idx = nbr[e];
        const float mk = vmask[e];
        const int p  = lane >> 1;      // row pair
        const int hf = lane & 1;       // half within pair
        const float4* pp = (const float4*)(pts + (b * HW_SZ + idx) * 64);
        #pragma unroll
        for (int i = 0; i < 16; i++) {
            float4 v = pp[i];
            v.x *= mk; v.y *= mk; v.z *= mk; v.w *= mk;
            #pragma unroll
            for (int j = 0; j < 4; j++) {
                int c = 4 * i + j;
                int sw = ((c >> 1) & 7) * 2;
                actwf[(c * 16 + (p ^ sw)) * 2 + hf] = (&v.x)[j];
            }
        }
        const float* cp = xyzs + (b * NS_SZ + n) * 3;
        const float* gx = xyz + (b * HW_SZ + idx) * 3;
        #pragma unroll
        for (int j = 0; j < 3; j++) {
            int c = 64 + j;
            int sw = ((c >> 1) & 7) * 2;
            actwf[(c * 16 + (p ^ sw)) * 2 + hf] = gx[j] * mk - cp[j];
        }
    }
    __syncwarp();

    // ---- layer 0: 67 -> 64 ----
    {
        ULL acc[32];
        #pragma unroll
        for (int j = 0; j < 32; j++) acc[j] = 0ull;
        run_layer(acc, actw, sm + OFF_W0, 67, 64, 0, lane);
        __syncwarp();
        epilogue_store(acc, actw, sm + OFF_T0, lane);
        __syncwarp();
    }

    // ---- layer 1: 64 -> 64 ----
    {
        ULL acc[32];
        #pragma unroll
        for (int j = 0; j < 32; j++) acc[j] = 0ull;
        run_layer(acc, actw, sm + OFF_W1, 64, 64, 0, lane);
        __syncwarp();
        epilogue_store(acc, actw, sm + OFF_T1, lane);
        __syncwarp();
    }

    // ---- layer 2: 64 -> 128 in two passes; thread-local max-pool; store ----
    const int grpbase = blockIdx.x * 32 + warp * 2;
    #pragma unroll
    for (int q = 0; q < 2; q++) {
        ULL acc[32];
        #pragma unroll
        for (int j = 0; j < 32; j++) acc[j] = 0ull;
        run_layer(acc, actw, sm + OFF_W2, 64, 128, 64 * q, lane);

        const float t0 = sm[OFF_T2 + 64 * q + 2 * lane];
        const float t1 = sm[OFF_T2 + 64 * q + 2 * lane + 1];
        #pragma unroll
        for (int g = 0; g < 2; g++) {
            float m0 = -1e30f, m1 = -1e30f;
            #pragma unroll
            for (int p = 8 * g; p < 8 * g + 8; p++) {
                float2 a = unpack2(acc[2 * p]);
                float2 b = unpack2(acc[2 * p + 1]);
                m0 = fmaxf(m0, fmaxf(a.x, a.y));
                m1 = fmaxf(m1, fmaxf(b.x, b.y));
            }
            float2 o;
            o.x = fmaxf(m0 + t0, 0.f);
            o.y = fmaxf(m1 + t1, 0.f);
            const long off = (long)(grpbase + g) * 128 + 64 * q + 2 * lane;
            *(float2*)(out + off) = o;
            if (copies > 1) *(float2*)(out + OUT_ONE + off) = o;
        }
    }
}

extern "C" void kernel_launch(void* const* d_in, const int* in_sizes, int n_in,
                              void* d_out, int out_size)
{
    const float* xyz   = (const float*)d_in[0];
    const float* pts   = (const float*)d_in[1];
    const float* xyzs  = (const float*)d_in[2];
    const int*   nbr   = (const int*)  d_in[3];
    const float* vmask = (const float*)d_in[4];
    const float* w0  = (const float*)d_in[5];
    const float* b0  = (const float*)d_in[6];
    const float* g0  = (const float*)d_in[7];
    const float* be0 = (const float*)d_in[8];
    const float* m0  = (const float*)d_in[9];
    const float* v0  = (const float*)d_in[10];
    const float* w1  = (const float*)d_in[11];
    const float* b1  = (const float*)d_in[12];
    const float* g1  = (const float*)d_in[13];
    const float* be1 = (const float*)d_in[14];
    const float* m1  = (const float*)d_in[15];
    const float* v1  = (const float*)d_in[16];
    const float* w2  = (const float*)d_in[17];
    const float* b2  = (const float*)d_in[18];
    const float* g2  = (const float*)d_in[19];
    const float* be2 = (const float*)d_in[20];
    const float* m2  = (const float*)d_in[21];
    const float* v2  = (const float*)d_in[22];

    int copies = (out_size >= 2 * OUT_ONE) ? 2 : 1;

    cudaFuncSetAttribute(pointnet_sa_kernel,
                         cudaFuncAttributeMaxDynamicSharedMemorySize, SMEM_BYTES);

    const int blocks = (4 * NS_SZ) / 32;   // 2048 blocks; 32 groups each
    pointnet_sa_kernel<<<blocks, THREADS, SMEM_BYTES>>>(
        xyz, pts, xyzs, nbr, vmask,
        w0, b0, g0, be0, m0, v0,
        w1, b1, g1, be1, m1, v1,
        w2, b2, g2, be2, m2, v2,
        (float*)d_out, copies);
}

// round 7
// speedup vs baseline: 1.6260x; 1.2057x over previous
#include <cuda_runtime.h>

// PointNetSaModule: gather(K=16) -> mask -> [67->64->64->128] MLP (BN folded) -> max over K.
// FFMA2 row-pair packing, thread tile = 8 row-pairs x 4 channels.
//  - half-warp (hi) selects pair half (= one K-group); broadcast act loads, conflict-free
//  - XOR swizzle has period 16 in cin: inner 16-cin block fully unrolled -> immediate offsets
//  - max over K=16 thread-local; coalesced float4 output

typedef unsigned long long ULL;

#define HW_SZ  65536
#define NS_SZ  16384
#define OUT_ONE (4 * 16384 * 128)

#define THREADS 512
#define WARPS   16

#define OFF_W0   0                  // 67*64 (rows permuted: feats 0..63, xyz-diff 64..66)
#define OFF_W1   4288
#define OFF_W2   (4288 + 4096)
#define OFF_T0   (OFF_W2 + 8192)
#define OFF_T1   (OFF_T0 + 64)
#define OFF_T2   (OFF_T1 + 64)
#define OFF_S0   (OFF_T2 + 128)
#define OFF_S1   (OFF_S0 + 64)
#define OFF_S2   (OFF_S1 + 64)
#define OFF_ACT  (OFF_S2 + 128)     // byte offset 68352, 16B aligned
#define ACT_ULL_PER_WARP 1088       // 68 cins x 16 pairs
#define SMEM_FLOATS (OFF_ACT + WARPS * 2 * ACT_ULL_PER_WARP)
#define SMEM_BYTES  (SMEM_FLOATS * 4)   // 207616

__device__ __forceinline__ ULL pack2_dup(float v) {
    ULL r; asm("mov.b64 %0, {%1, %1};" : "=l"(r) : "f"(v)); return r;
}
__device__ __forceinline__ ULL pack2(float a, float b) {
    ULL r; asm("mov.b64 %0, {%1, %2};" : "=l"(r) : "f"(a), "f"(b)); return r;
}
__device__ __forceinline__ float2 unpack2(ULL v) {
    float2 f; asm("mov.b64 {%0, %1}, %2;" : "=f"(f.x), "=f"(f.y) : "l"(v)); return f;
}
__device__ __forceinline__ void ffma2(ULL& acc, ULL x, ULL w) {
    asm("fma.rn.f32x2 %0, %1, %2, %0;" : "+l"(acc) : "l"(x), "l"(w));
}

// act layout: ULL index = c*16 + (pair ^ sw(c)),  sw(c) = ((c>>1)&7)*2  (even -> pairs stay
// ulonglong2-adjacent). physical = [(8hi)^(sw&8)] + [(2r)^(sw&6)] (disjoint bits).

// One cin at unroll slot u (sw compile-time after unroll). pA = actw + 8*hi, pB = actw + 8 - 8*hi.
#define RUN_CIN(u, WS) do {                                                     \
    const int sw  = (((u) >> 1) & 7) * 2;                                       \
    const ULL* xr = ((sw & 8) ? pB : pA) + (u) * 16;                            \
    ulonglong2 x0 = *(const ulonglong2*)(xr + (0 ^ (sw & 6)));                  \
    ulonglong2 x1 = *(const ulonglong2*)(xr + (2 ^ (sw & 6)));                  \
    ulonglong2 x2 = *(const ulonglong2*)(xr + (4 ^ (sw & 6)));                  \
    ulonglong2 x3 = *(const ulonglong2*)(xr + (6 ^ (sw & 6)));                  \
    float4 wv = *(const float4*)(wl + (u) * (WS));                              \
    ULL w0 = pack2_dup(wv.x), w1 = pack2_dup(wv.y);                             \
    ULL w2 = pack2_dup(wv.z), w3 = pack2_dup(wv.w);                             \
    ffma2(acc[ 0], x0.x, w0); ffma2(acc[ 1], x0.x, w1);                         \
    ffma2(acc[ 2], x0.x, w2); ffma2(acc[ 3], x0.x, w3);                         \
    ffma2(acc[ 4], x0.y, w0); ffma2(acc[ 5], x0.y, w1);                         \
    ffma2(acc[ 6], x0.y, w2); ffma2(acc[ 7], x0.y, w3);                         \
    ffma2(acc[ 8], x1.x, w0); ffma2(acc[ 9], x1.x, w1);                         \
    ffma2(acc[10], x1.x, w2); ffma2(acc[11], x1.x, w3);                         \
    ffma2(acc[12], x1.y, w0); ffma2(acc[13], x1.y, w1);                         \
    ffma2(acc[14], x1.y, w2); ffma2(acc[15], x1.y, w3);                         \
    ffma2(acc[16], x2.x, w0); ffma2(acc[17], x2.x, w1);                         \
    ffma2(acc[18], x2.x, w2); ffma2(acc[19], x2.x, w3);                         \
    ffma2(acc[20], x2.y, w0); ffma2(acc[21], x2.y, w1);                         \
    ffma2(acc[22], x2.y, w2); ffma2(acc[23], x2.y, w3);                         \
    ffma2(acc[24], x3.x, w0); ffma2(acc[25], x3.x, w1);                         \
    ffma2(acc[26], x3.x, w2); ffma2(acc[27], x3.x, w3);                         \
    ffma2(acc[28], x3.y, w0); ffma2(acc[29], x3.y, w1);                         \
    ffma2(acc[30], x3.y, w2); ffma2(acc[31], x3.y, w3);                         \
} while (0)

// NCIN = 16*NB + NR cins; WS = weight row stride (floats)
template<int NB, int NR, int WS>
__device__ __forceinline__ void run_layer(ULL acc[32], const ULL* pA, const ULL* pB,
                                          const float* wl)
{
    #pragma unroll
    for (int j = 0; j < 32; j++) acc[j] = 0ull;
    #pragma unroll 1
    for (int t = 0; t < NB; t++) {
        #pragma unroll
        for (int u = 0; u < 16; u++) RUN_CIN(u, WS);
        pA += 256; pB += 256; wl += 16 * WS;
    }
    #pragma unroll
    for (int u = 0; u < NR; u++) RUN_CIN(u, WS);
}

__global__ void __launch_bounds__(THREADS, 1)
pointnet_sa_kernel(
    const float* __restrict__ xyz, const float* __restrict__ pts,
    const float* __restrict__ xyzs, const int* __restrict__ nbr,
    const float* __restrict__ vmask,
    const float* __restrict__ w0, const float* __restrict__ b0,
    const float* __restrict__ g0, const float* __restrict__ be0,
    const float* __restrict__ m0, const float* __restrict__ v0,
    const float* __restrict__ w1, const float* __restrict__ b1,
    const float* __restrict__ g1, const float* __restrict__ be1,
    const float* __restrict__ m1, const float* __restrict__ v1,
    const float* __restrict__ w2, const float* __restrict__ b2,
    const float* __restrict__ g2, const float* __restrict__ be2,
    const float* __restrict__ m2, const float* __restrict__ v2,
    float* __restrict__ out, int copies)
{
    extern __shared__ float sm[];
    const int tid = threadIdx.x;

    // ---- BN fold ----
    if (tid < 64) {
        float s = g0[tid] * rsqrtf(v0[tid] + 1e-5f);
        sm[OFF_S0 + tid] = s;
        sm[OFF_T0 + tid] = (b0[tid] - m0[tid]) * s + be0[tid];
        float s1 = g1[tid] * rsqrtf(v1[tid] + 1e-5f);
        sm[OFF_S1 + tid] = s1;
        sm[OFF_T1 + tid] = (b1[tid] - m1[tid]) * s1 + be1[tid];
    }
    if (tid < 128) {
        float s = g2[tid] * rsqrtf(v2[tid] + 1e-5f);
        sm[OFF_S2 + tid] = s;
        sm[OFF_T2 + tid] = (b2[tid] - m2[tid]) * s + be2[tid];
    }
    __syncthreads();
    for (int i = tid; i < 4288; i += THREADS) {
        int r = i >> 6, c = i & 63;
        int sr = (r < 64) ? (r + 3) : (r - 64);   // feats first, xyz-diff rows last
        sm[OFF_W0 + i] = w0[sr * 64 + c] * sm[OFF_S0 + c];
    }
    for (int i = tid; i < 4096; i += THREADS) sm[OFF_W1 + i] = w1[i] * sm[OFF_S1 + (i & 63)];
    for (int i = tid; i < 8192; i += THREADS) sm[OFF_W2 + i] = w2[i] * sm[OFF_S2 + (i & 127)];
    __syncthreads();

    const int lane = tid & 31;
    const int warp = tid >> 5;
    const int lh   = lane & 15;   // channel lane: ch = 4*lh .. 4*lh+3
    const int hi   = lane >> 4;   // pair half / K-group selector
    ULL* actw = (ULL*)(sm + OFF_ACT) + warp * ACT_ULL_PER_WARP;
    float* actwf = (float*)actw;

    // ---- gather: lane owns row=lane (rows 0-15 -> group hi=0, 16-31 -> hi=1) ----
    {
        const int grp = blockIdx.x * 32 + warp * 2 + (lane >> 4);
        const int b = grp >> 14;
        const int n = grp & (NS_SZ - 1);
        const int e = grp * 16 + (lane & 15);
        const int idx = nbr[e];
        const float mk = vmask[e];
        const int p  = lane >> 1;
        const int hf = lane & 1;
        const float4* pp = (const float4*)(pts + (b * HW_SZ + idx) * 64);
        #pragma unroll
        for (int i = 0; i < 16; i++) {
            float4 v = pp[i];
            v.x *= mk; v.y *= mk; v.z *= mk; v.w *= mk;
            #pragma unroll
            for (int j = 0; j < 4; j++) {
                int c = 4 * i + j;
                int sw = ((c >> 1) & 7) * 2;
                actwf[(c * 16 + (p ^ sw)) * 2 + hf] = (&v.x)[j];
            }
        }
        const float* cp = xyzs + (b * NS_SZ + n) * 3;
        const float* gx = xyz + (b * HW_SZ + idx) * 3;
        #pragma unroll
        for (int j = 0; j < 3; j++) {
            int c = 64 + j;
            int sw = ((c >> 1) & 7) * 2;
            actwf[(c * 16 + (p ^ sw)) * 2 + hf] = gx[j] * mk - cp[j];
        }
    }
    __syncwarp();

    const ULL* pA = actw + 8 * hi;
    const ULL* pB = actw + 8 - 8 * hi;

    // epilogue swizzles for this thread's output cins c' = 4lh..4lh+3
    const int sw01 = ((lh * 2) & 7) * 2;
    const int sw23 = ((lh * 2 + 1) & 7) * 2;
    ULL* row0 = actw + (4 * lh + 0) * 16;
    ULL* row1 = actw + (4 * lh + 1) * 16;
    ULL* row2 = actw + (4 * lh + 2) * 16;
    ULL* row3 = actw + (4 * lh + 3) * 16;

    // ---- layers 0 and 1 ----
    #pragma unroll 1
    for (int L = 0; L < 2; L++) {
        ULL acc[32];
        if (L == 0) run_layer<4, 3, 64>(acc, pA, pB, sm + OFF_W0 + 4 * lh);
        else        run_layer<4, 0, 64>(acc, pA, pB, sm + OFF_W1 + 4 * lh);
        float4 bt = *(const float4*)(sm + (L == 0 ? OFF_T0 : OFF_T1) + 4 * lh);
        __syncwarp();
        #pragma unroll
        for (int q = 0; q < 8; q++) {
            const int p = 8 * hi + q;
            const int i01 = p ^ sw01, i23 = p ^ sw23;
            float2 a;
            a = unpack2(acc[4*q+0]); row0[i01] = pack2(fmaxf(a.x+bt.x,0.f), fmaxf(a.y+bt.x,0.f));
            a = unpack2(acc[4*q+1]); row1[i01] = pack2(fmaxf(a.x+bt.y,0.f), fmaxf(a.y+bt.y,0.f));
            a = unpack2(acc[4*q+2]); row2[i23] = pack2(fmaxf(a.x+bt.z,0.f), fmaxf(a.y+bt.z,0.f));
            a = unpack2(acc[4*q+3]); row3[i23] = pack2(fmaxf(a.x+bt.w,0.f), fmaxf(a.y+bt.w,0.f));
        }
        __syncwarp();
    }

    // ---- layer 2 (two 64-ch passes) + thread-local max over K + store ----
    const int grp = blockIdx.x * 32 + warp * 2 + hi;
    #pragma unroll 1
    for (int pass = 0; pass < 2; pass++) {
        ULL acc[32];
        run_layer<4, 0, 128>(acc, pA, pB, sm + OFF_W2 + 64 * pass + 4 * lh);
        float4 bt = *(const float4*)(sm + OFF_T2 + 64 * pass + 4 * lh);
        float4 o;
        #pragma unroll
        for (int j = 0; j < 4; j++) {
            float m = -1e30f;
            #pragma unroll
            for (int q = 0; q < 8; q++) {
                float2 a = unpack2(acc[4*q + j]);
                m = fmaxf(m, fmaxf(a.x, a.y));
            }
            (&o.x)[j] = fmaxf(m + (&bt.x)[j], 0.f);
        }
        const long off = (long)grp * 128 + 64 * pass + 4 * lh;
        *(float4*)(out + off) = o;
        if (copies > 1) *(float4*)(out + OUT_ONE + off) = o;
    }
}

extern "C" void kernel_launch(void* const* d_in, const int* in_sizes, int n_in,
                              void* d_out, int out_size)
{
    const float* xyz   = (const float*)d_in[0];
    const float* pts   = (const float*)d_in[1];
    const float* xyzs  = (const float*)d_in[2];
    const int*   nbr   = (const int*)  d_in[3];
    const float* vmask = (const float*)d_in[4];
    const float* w0  = (const float*)d_in[5];
    const float* b0  = (const float*)d_in[6];
    const float* g0  = (const float*)d_in[7];
    const float* be0 = (const float*)d_in[8];
    const float* m0  = (const float*)d_in[9];
    const float* v0  = (const float*)d_in[10];
    const float* w1  = (const float*)d_in[11];
    const float* b1  = (const float*)d_in[12];
    const float* g1  = (const float*)d_in[13];
    const float* be1 = (const float*)d_in[14];
    const float* m1  = (const float*)d_in[15];
    const float* v1  = (const float*)d_in[16];
    const float* w2  = (const float*)d_in[17];
    const float* b2  = (const float*)d_in[18];
    const float* g2  = (const float*)d_in[19];
    const float* be2 = (const float*)d_in[20];
    const float* m2  = (const float*)d_in[21];
    const float* v2  = (const float*)d_in[22];

    int copies = (out_size >= 2 * OUT_ONE) ? 2 : 1;

    cudaFuncSetAttribute(pointnet_sa_kernel,
                         cudaFuncAttributeMaxDynamicSharedMemorySize, SMEM_BYTES);

    const int blocks = (4 * NS_SZ) / 32;   // 2048
    pointnet_sa_kernel<<<blocks, THREADS, SMEM_BYTES>>>(
        xyz, pts, xyzs, nbr, vmask,
        w0, b0, g0, be0, m0, v0,
        w1, b1, g1, be1, m1, v1,
        w2, b2, g2, be2, m2, v2,
        (float*)d_out, copies);
}